// round 1
// baseline (speedup 1.0000x reference)
#include <cuda_runtime.h>

#define NSEG 2048
#define EPS 1e-6f

// Per-segment scratch (no device mallocs allowed).
__device__ float g_sum_s[NSEG];
__device__ float g_sum_s2[NSEG];
__device__ float g_sum_v2[NSEG];
__device__ float g_cnt[NSEG];
__device__ float g_m[NSEG];
__device__ float g_invvar[NSEG];
__device__ float g_invvm[NSEG];

__global__ void zero_kernel() {
    int i = blockIdx.x * blockDim.x + threadIdx.x;
    if (i < NSEG) {
        g_sum_s[i]  = 0.0f;
        g_sum_s2[i] = 0.0f;
        g_sum_v2[i] = 0.0f;
        g_cnt[i]    = 0.0f;
    }
}

// One warp per node: 2 float4 of s (64 f4/node) per lane? -> 64 f4 over 32 lanes = 2 each;
// v: 96 f4 over 32 lanes = 3 each. Warp-reduce, lane 0 does 4 atomics.
__global__ void accum_kernel(const float* __restrict__ s,
                             const float* __restrict__ v,
                             const int*   __restrict__ batch,
                             int n) {
    int warp = (blockIdx.x * blockDim.x + threadIdx.x) >> 5;
    int lane = threadIdx.x & 31;
    if (warp >= n) return;

    const float4* s4 = reinterpret_cast<const float4*>(s) + (size_t)warp * 64;
    const float4* v4 = reinterpret_cast<const float4*>(v) + (size_t)warp * 96;

    float ss = 0.0f, ss2 = 0.0f, sv2 = 0.0f;
#pragma unroll
    for (int i = 0; i < 2; i++) {
        float4 a = s4[lane + 32 * i];
        ss  += a.x + a.y + a.z + a.w;
        ss2 += a.x * a.x + a.y * a.y + a.z * a.z + a.w * a.w;
    }
#pragma unroll
    for (int i = 0; i < 3; i++) {
        float4 b = v4[lane + 32 * i];
        sv2 += b.x * b.x + b.y * b.y + b.z * b.z + b.w * b.w;
    }

#pragma unroll
    for (int o = 16; o > 0; o >>= 1) {
        ss  += __shfl_xor_sync(0xFFFFFFFFu, ss,  o);
        ss2 += __shfl_xor_sync(0xFFFFFFFFu, ss2, o);
        sv2 += __shfl_xor_sync(0xFFFFFFFFu, sv2, o);
    }

    if (lane == 0) {
        int b = batch[warp];
        atomicAdd(&g_sum_s[b],  ss);
        atomicAdd(&g_sum_s2[b], ss2);
        atomicAdd(&g_sum_v2[b], sv2);
        atomicAdd(&g_cnt[b],    1.0f);
    }
}

__global__ void finalize_kernel() {
    int i = blockIdx.x * blockDim.x + threadIdx.x;
    if (i >= NSEG) return;
    float cnt = fmaxf(g_cnt[i], 1.0f);
    float denom_s = cnt * 256.0f;
    float m = g_sum_s[i] / denom_s;
    float var = g_sum_s2[i] / denom_s - m * m;
    var = fmaxf(var, EPS);
    float vmean = g_sum_v2[i] / (cnt * 128.0f);
    vmean = fmaxf(vmean, EPS);
    g_m[i]      = m;
    g_invvar[i] = 1.0f / var;
    g_invvm[i]  = 1.0f / vmean;
}

// sout = (s - m[b]) * invvar[b] * weight + bias ; float4 over n*64 elements
__global__ void apply_s_kernel(const float* __restrict__ s,
                               const float* __restrict__ weight,
                               const float* __restrict__ bias,
                               const int*   __restrict__ batch,
                               float* __restrict__ out,
                               int total4) {
    int idx = blockIdx.x * blockDim.x + threadIdx.x;
    if (idx >= total4) return;
    int node = idx >> 6;        // 64 float4 per node
    int cg   = idx & 63;
    int b = batch[node];
    float m  = g_m[b];
    float iv = g_invvar[b];
    float4 a  = reinterpret_cast<const float4*>(s)[idx];
    float4 w4 = reinterpret_cast<const float4*>(weight)[cg];
    float4 b4 = reinterpret_cast<const float4*>(bias)[cg];
    float4 o;
    o.x = (a.x - m) * iv * w4.x + b4.x;
    o.y = (a.y - m) * iv * w4.y + b4.y;
    o.z = (a.z - m) * iv * w4.z + b4.z;
    o.w = (a.w - m) * iv * w4.w + b4.w;
    reinterpret_cast<float4*>(out)[idx] = o;
}

// vout = v * invvm[b] ; float4 over n*96 elements
__global__ void apply_v_kernel(const float* __restrict__ v,
                               const int*   __restrict__ batch,
                               float* __restrict__ out,
                               int total4) {
    int idx = blockIdx.x * blockDim.x + threadIdx.x;
    if (idx >= total4) return;
    int node = idx / 96;        // 96 float4 per node (compiler -> mul/shift)
    int b = batch[node];
    float iv = g_invvm[b];
    float4 a = reinterpret_cast<const float4*>(v)[idx];
    float4 o;
    o.x = a.x * iv;
    o.y = a.y * iv;
    o.z = a.z * iv;
    o.w = a.w * iv;
    reinterpret_cast<float4*>(out)[idx] = o;
}

extern "C" void kernel_launch(void* const* d_in, const int* in_sizes, int n_in,
                              void* d_out, int out_size) {
    const float* s      = (const float*)d_in[0];
    const float* v      = (const float*)d_in[1];
    const float* weight = (const float*)d_in[2];
    const float* bias   = (const float*)d_in[3];
    const int*   batch  = (const int*)d_in[4];

    int n = in_sizes[4];                 // number of nodes
    float* out_s = (float*)d_out;        // [n, 256]
    float* out_v = out_s + (size_t)n * 256;  // [n, 3, 128]

    zero_kernel<<<(NSEG + 255) / 256, 256>>>();

    // 8 warps (nodes) per 256-thread block
    int blocks = (n + 7) / 8;
    accum_kernel<<<blocks, 256>>>(s, v, batch, n);

    finalize_kernel<<<(NSEG + 255) / 256, 256>>>();

    int s_total4 = n * 64;
    apply_s_kernel<<<(s_total4 + 255) / 256, 256>>>(s, weight, bias, batch, out_s, s_total4);

    int v_total4 = n * 96;
    apply_v_kernel<<<(v_total4 + 255) / 256, 256>>>(v, batch, out_v, v_total4);
}